// round 16
// baseline (speedup 1.0000x reference)
#include <cuda_runtime.h>
#include <cuda_fp16.h>

#define NN 50000
#define RR 4
#define EE 400000
#define NR (RR * NN)              // 200000 (relation,node) pairs
#define NB1 ((NR + 1023) / 1024)  // scan blocks over (r,node) pairs (196)

// ---- scratch (static __device__; no allocation) ----
__device__ __half g_h[NN * 128];     // current layer input features (fp16)
__device__ __half g_G[NN * 256];     // aggregated features [G0 | G1] (fp16)
__device__ __half g_Bh[(128 + 128 + 64) * 264];  // fp16 weights, [n][264]
__device__ int    g_deg [2 * NR];    // [out: r*NN+s] then [in: NR + r*NN+d]
__device__ float  g_norm[2 * NR];    // rsqrt(max(deg,1)) same layout
__device__ int    g_off[NR + 1];     // CSR offsets by (r,dst)
__device__ int    g_cur[NR];         // fill cursors
__device__ int2   g_epk[RR * EE];    // packed edge: {src, bitcast(n_out[r][src])}
__device__ int    g_bsum[256];       // raw per-block sums from scan1

// ---------------- fused pre-pass: zero degrees, x->fp16, bases->fp16 ------------
// basis branch: n fast-varying so B reads are coalesced (writes take the stride)
__global__ void k_pre(const float* __restrict__ x,
                      const float* __restrict__ b0,
                      const float* __restrict__ b1,
                      const float* __restrict__ b2) {
    const int Z0 = 2 * NR;
    const int C0 = Z0 + NN * 128;
    const int W0 = C0 + 128 * 256;
    const int W1 = W0 + 128 * 256;
    const int W2 = W1 + 64 * 256;
    int i = blockIdx.x * blockDim.x + threadIdx.x;
    if (i < Z0) {
        g_deg[i] = 0;
    } else if (i < C0) {
        int j = i - Z0;
        g_h[j] = __float2half(x[j]);
    } else if (i < W0) {           // basis0: DO=128
        int j = i - C0;
        int n = j & 127, kk = j >> 7;           // n fast -> coalesced read
        g_Bh[n * 264 + kk] =
            __float2half(b0[((kk >> 7) * 128 + (kk & 127)) * 128 + n]);
    } else if (i < W1) {           // basis1: DO=128
        int j = i - W0;
        int n = j & 127, kk = j >> 7;
        g_Bh[128 * 264 + n * 264 + kk] =
            __float2half(b1[((kk >> 7) * 128 + (kk & 127)) * 128 + n]);
    } else if (i < W2) {           // basis2: DO=64
        int j = i - W1;
        int n = j & 63, kk = j >> 6;
        g_Bh[256 * 264 + n * 264 + kk] =
            __float2half(b2[((kk >> 7) * 128 + (kk & 127)) * 64 + n]);
    }
}

// ---------------- degree count ----------------
__global__ void k_count(const int* __restrict__ src, const int* __restrict__ dst) {
    int i = blockIdx.x * blockDim.x + threadIdx.x;
    if (i >= RR * EE) return;
    int r = i / EE;
    atomicAdd(&g_deg[r * NN + src[i]], 1);        // out-degree (r,s)
    atomicAdd(&g_deg[NR + r * NN + dst[i]], 1);   // in-degree  (r,d)
}

// ---------------- CSR build (counting sort by (r,dst)) + norms ----------------
// scan1: norms + per-block INCLUSIVE scan; writes local-exclusive prefix to g_off
__global__ void __launch_bounds__(1024)
k_scan1() {
    __shared__ int sh[1024];
    int i = blockIdx.x * 1024 + threadIdx.x;
    int t = threadIdx.x;
    int din = 0;
    if (i < NR) {
        int dout = g_deg[i];
        din = g_deg[NR + i];
        g_norm[i]      = rsqrtf((float)max(dout, 1));
        g_norm[NR + i] = rsqrtf((float)max(din, 1));
    }
    sh[t] = din;
    __syncthreads();
    for (int s = 1; s < 1024; s <<= 1) {
        int u = (t >= s) ? sh[t - s] : 0;
        __syncthreads();
        sh[t] += u;
        __syncthreads();
    }
    if (i < NR) g_off[i] = sh[t] - din;      // local exclusive prefix
    if (t == 1023) g_bsum[blockIdx.x] = sh[1023];   // block total
}

// scanfix: add cross-block prefix to local prefixes; init cursors + total
__global__ void __launch_bounds__(1024)
k_scanfix() {
    __shared__ int sb[256];
    int t = threadIdx.x;
    if (t < 256) sb[t] = (t < NB1) ? g_bsum[t] : 0;
    __syncthreads();
    if (t < 256) {   // inclusive scan of the 196 block sums
        for (int s = 1; s < 256; s <<= 1) {
            int v = (t >= s) ? sb[t - s] : 0;
            __syncthreads();
            sb[t] += v;
            __syncthreads();
        }
    } else {
        for (int s = 1; s < 256; s <<= 1) { __syncthreads(); __syncthreads(); }
    }
    int blkpref = (blockIdx.x == 0) ? 0 : sb[blockIdx.x - 1];

    int i = blockIdx.x * 1024 + t;
    if (i < NR) {
        int ex = g_off[i] + blkpref;
        g_off[i] = ex;
        g_cur[i] = ex;
    }
    if (i == 0) g_off[NR] = sb[NB1 - 1];     // grand total
}

__global__ void k_fill(const int* __restrict__ src, const int* __restrict__ dst) {
    int i = blockIdx.x * blockDim.x + threadIdx.x;
    if (i >= RR * EE) return;
    int r = i / EE;
    int s = src[i], d = dst[i];
    int pos = atomicAdd(&g_cur[r * NN + d], 1);
    int2 p;
    p.x = s;
    p.y = __float_as_int(g_norm[r * NN + s]);   // n_out[r][s]
    g_epk[pos] = p;
}

// ---------------- aggregation: warp per node, per-relation segments (R7) -------
__device__ __forceinline__ void accA(float4& acc, uint2 pk, float we) {
    float2 f0 = __half22float2(*(__half2*)&pk.x);
    float2 f1 = __half22float2(*(__half2*)&pk.y);
    acc.x = fmaf(we, f0.x, acc.x);
    acc.y = fmaf(we, f0.y, acc.y);
    acc.z = fmaf(we, f1.x, acc.z);
    acc.w = fmaf(we, f1.y, acc.w);
}

__global__ void __launch_bounds__(256)
k_agg(const __half* __restrict__ h, const float* __restrict__ coeff,
      __half* __restrict__ G) {
    int w = (blockIdx.x * 256 + threadIdx.x) >> 5;   // node id
    int lane = threadIdx.x & 31;
    if (w >= NN) return;
    float4 g0 = make_float4(0.f, 0.f, 0.f, 0.f);
    float4 g1 = make_float4(0.f, 0.f, 0.f, 0.f);
#pragma unroll
    for (int r = 0; r < RR; r++) {
        int idx = r * NN + w;
        int beg = g_off[idx], end = g_off[idx + 1];
        float4 acc = make_float4(0.f, 0.f, 0.f, 0.f);
        int e = beg;
        // 4-way unroll: 4 descriptor loads, then 4 independent gathers (MLP=4)
        for (; e + 4 <= end; e += 4) {
            int2 p0 = g_epk[e],     p1 = g_epk[e + 1];
            int2 p2 = g_epk[e + 2], p3 = g_epk[e + 3];
            uint2 a = ((const uint2*)(h + p0.x * 128))[lane];
            uint2 b = ((const uint2*)(h + p1.x * 128))[lane];
            uint2 c = ((const uint2*)(h + p2.x * 128))[lane];
            uint2 d = ((const uint2*)(h + p3.x * 128))[lane];
            accA(acc, a, __int_as_float(p0.y));
            accA(acc, b, __int_as_float(p1.y));
            accA(acc, c, __int_as_float(p2.y));
            accA(acc, d, __int_as_float(p3.y));
        }
        for (; e < end; e++) {
            int2 p = g_epk[e];
            uint2 a = ((const uint2*)(h + p.x * 128))[lane];
            accA(acc, a, __int_as_float(p.y));
        }
        float ni = g_norm[NR + idx];
        float s0 = ni * coeff[2 * r];
        float s1 = ni * coeff[2 * r + 1];
        g0.x = fmaf(s0, acc.x, g0.x); g0.y = fmaf(s0, acc.y, g0.y);
        g0.z = fmaf(s0, acc.z, g0.z); g0.w = fmaf(s0, acc.w, g0.w);
        g1.x = fmaf(s1, acc.x, g1.x); g1.y = fmaf(s1, acc.y, g1.y);
        g1.z = fmaf(s1, acc.z, g1.z); g1.w = fmaf(s1, acc.w, g1.w);
    }
    __half2 h0 = __floats2half2_rn(g0.x, g0.y), h1 = __floats2half2_rn(g0.z, g0.w);
    __half2 h2 = __floats2half2_rn(g1.x, g1.y), h3 = __floats2half2_rn(g1.z, g1.w);
    uint2 u0, u1;
    u0.x = *(unsigned*)&h0; u0.y = *(unsigned*)&h1;
    u1.x = *(unsigned*)&h2; u1.y = *(unsigned*)&h3;
    ((uint2*)(G + w * 256))[lane]       = u0;   // G0
    ((uint2*)(G + w * 256 + 128))[lane] = u1;   // G1
}

// ---------------- tensor-core GEMM: G[N,256](fp16) @ B -> out ----------------
// A prefetch + double-buffered A staging: one __syncthreads per k-step.
template<int DO, bool RELU, bool TOHALF>
__global__ void __launch_bounds__(256)
k_gemm_tc(const __half* __restrict__ G, const __half* __restrict__ Bh,
          void* __restrict__ outp) {
    __shared__ __half Bs[64 * 264];      // [n][k], stride 264 halves
    __shared__ __half As[2][128 * 24];   // double-buffered A staging

    int tid  = threadIdx.x;
    int warp = tid >> 5, lane = tid & 31;
    int row0 = blockIdx.x * 128;
    int col0 = blockIdx.y * 64;

    const uint4* gB = (const uint4*)(Bh + col0 * 264);
    for (int i = tid; i < 64 * 33; i += 256)
        ((uint4*)Bs)[i] = gB[i];

    float acc[8][4];
#pragma unroll
    for (int n = 0; n < 8; n++)
#pragma unroll
        for (int j = 0; j < 4; j++) acc[n][j] = 0.f;

    int arow = tid >> 1, aseg = tid & 1;
    int grow = row0 + arow;
    const __half* gA = G + grow * 256 + aseg * 8;
    __half* asd0 = &As[0][arow * 24 + aseg * 8];
    __half* asd1 = &As[1][arow * 24 + aseg * 8];
    bool aok = grow < NN;

    unsigned ald0 = (unsigned)__cvta_generic_to_shared(
        &As[0][(warp * 16 + (lane & 15)) * 24 + (lane >> 4) * 8]);
    unsigned ald1 = ald0 + 128 * 24 * 2;
    int bn = lane >> 2, bk = (lane & 3) * 2;

    // prologue: stage k-step 0 into buf0, prefetch k-step 1
    uint4 v = make_uint4(0u, 0u, 0u, 0u);
    if (aok) v = *(const uint4*)gA;
    *(uint4*)asd0 = v;
    v = make_uint4(0u, 0u, 0u, 0u);
    if (aok) v = *(const uint4*)(gA + 16);
    __syncthreads();   // covers Bs staging + buf0

    for (int ks = 0; ks < 16; ks++) {
        int k0 = ks * 16;
        // stage next k-step into the other buffer (read last at ks-1, safe)
        if (ks < 15) {
            *(uint4*)(((ks + 1) & 1) ? asd1 : asd0) = v;
            if (ks < 14) {
                v = make_uint4(0u, 0u, 0u, 0u);
                if (aok) v = *(const uint4*)(gA + (ks + 2) * 16);
            }
        }

        unsigned a0, a1, a2, a3;
        asm volatile("ldmatrix.sync.aligned.m8n8.x4.shared.b16 {%0,%1,%2,%3}, [%4];"
                     : "=r"(a0), "=r"(a1), "=r"(a2), "=r"(a3)
                     : "r"((ks & 1) ? ald1 : ald0));
#pragma unroll
        for (int nt = 0; nt < 8; nt++) {
            const __half* bp = Bs + (nt * 8 + bn) * 264 + k0 + bk;
            unsigned b0 = *(const unsigned*)bp;
            unsigned b1 = *(const unsigned*)(bp + 8);
            asm volatile(
                "mma.sync.aligned.m16n8k16.row.col.f32.f16.f16.f32 "
                "{%0,%1,%2,%3}, {%4,%5,%6,%7}, {%8,%9}, {%0,%1,%2,%3};"
                : "+f"(acc[nt][0]), "+f"(acc[nt][1]), "+f"(acc[nt][2]), "+f"(acc[nt][3])
                : "r"(a0), "r"(a1), "r"(a2), "r"(a3), "r"(b0), "r"(b1));
        }
        __syncthreads();   // publish next buffer / retire this one
    }

    int rlo = row0 + warp * 16 + (lane >> 2);
    int cb  = col0 + (lane & 3) * 2;
#pragma unroll
    for (int nt = 0; nt < 8; nt++) {
        int c = cb + nt * 8;
        float d0 = acc[nt][0], d1 = acc[nt][1], d2 = acc[nt][2], d3 = acc[nt][3];
        if (RELU) {
            d0 = fmaxf(d0, 0.f); d1 = fmaxf(d1, 0.f);
            d2 = fmaxf(d2, 0.f); d3 = fmaxf(d3, 0.f);
        }
        if (TOHALF) {
            __half* o = (__half*)outp;
            if (rlo < NN)     *(__half2*)(o + rlo * DO + c)       = __floats2half2_rn(d0, d1);
            if (rlo + 8 < NN) *(__half2*)(o + (rlo + 8) * DO + c) = __floats2half2_rn(d2, d3);
        } else {
            float* o = (float*)outp;
            if (rlo < NN)     { o[rlo * DO + c] = d0;       o[rlo * DO + c + 1] = d1; }
            if (rlo + 8 < NN) { o[(rlo + 8) * DO + c] = d2; o[(rlo + 8) * DO + c + 1] = d3; }
        }
    }
}

// ---------------- launch ----------------
extern "C" void kernel_launch(void* const* d_in, const int* in_sizes, int n_in,
                              void* d_out, int out_size) {
    const float* x   = (const float*)d_in[0];
    const int*   src = (const int*)  d_in[1];
    const int*   dst = (const int*)  d_in[2];
    const float* b0  = (const float*)d_in[3];
    const float* c0  = (const float*)d_in[4];
    const float* b1  = (const float*)d_in[5];
    const float* c1  = (const float*)d_in[6];
    const float* b2  = (const float*)d_in[7];
    const float* c2  = (const float*)d_in[8];
    float* out = (float*)d_out;

    __half *h, *G, *Bh;
    cudaGetSymbolAddress((void**)&h,  g_h);
    cudaGetSymbolAddress((void**)&G,  g_G);
    cudaGetSymbolAddress((void**)&Bh, g_Bh);
    __half* Bh0 = Bh;
    __half* Bh1 = Bh + 128 * 264;
    __half* Bh2 = Bh + 256 * 264;

    const int preN    = 2 * NR + NN * 128 + 128 * 256 + 128 * 256 + 64 * 256;
    const int edgeTh  = (RR * EE + 255) / 256;
    const int aggGrid = (NN * 32 + 255) / 256;       // 1 warp per node
    const dim3 gemm2(391, 2), gemm1(391, 1);

    // preprocessing (every call: deterministic)
    k_pre<<<(preN + 255) / 256, 256>>>(x, b0, b1, b2);
    k_count<<<edgeTh, 256>>>(src, dst);
    k_scan1<<<NB1, 1024>>>();
    k_scanfix<<<NB1, 1024>>>();
    k_fill<<<edgeTh, 256>>>(src, dst);

    // layer 0
    k_agg<<<aggGrid, 256>>>(h, c0, G);
    k_gemm_tc<128, true, true><<<gemm2, 256>>>(G, Bh0, h);
    // layer 1
    k_agg<<<aggGrid, 256>>>(h, c1, G);
    k_gemm_tc<128, true, true><<<gemm2, 256>>>(G, Bh1, h);
    // layer 2: final, fp32, no relu
    k_agg<<<aggGrid, 256>>>(h, c2, G);
    k_gemm_tc<64, false, false><<<gemm1, 256>>>(G, Bh2, out);
}

// round 17
// speedup vs baseline: 1.0125x; 1.0125x over previous
#include <cuda_runtime.h>
#include <cuda_fp16.h>

#define NN 50000
#define RR 4
#define EE 400000
#define NR (RR * NN)              // 200000 (relation,node) pairs
#define NB1 ((NR + 1023) / 1024)  // scan blocks over (r,node) pairs (196)

// ---- scratch (static __device__; no allocation) ----
__device__ __half    g_h[NN * 128];     // current layer input features (fp16)
__device__ __half    g_G[NN * 256];     // aggregated features [G0 | G1] (fp16)
__device__ __half    g_Bh[(128 + 128 + 64) * 264];  // fp16 weights, [n][264]
__device__ int       g_deg [2 * NR];    // [out: r*NN+s] then [in: NR + r*NN+d]
__device__ float     g_norm[2 * NR];    // rsqrt(max(deg,1)) same layout
__device__ int       g_off[NR + 1];     // CSR offsets by (r,dst)
__device__ int       g_cur[NR];         // fill cursors
__device__ unsigned  g_epk[RR * EE];    // packed edge: src:u16 | fp16(n_out)<<16
__device__ int       g_bsum[256];       // raw per-block sums from scan1

// ---------------- fused pre-pass: zero degrees, x->fp16, bases->fp16 ------------
__global__ void k_pre(const float* __restrict__ x,
                      const float* __restrict__ b0,
                      const float* __restrict__ b1,
                      const float* __restrict__ b2) {
    const int Z0 = 2 * NR;
    const int C0 = Z0 + NN * 128;
    const int W0 = C0 + 128 * 256;
    const int W1 = W0 + 128 * 256;
    const int W2 = W1 + 64 * 256;
    int i = blockIdx.x * blockDim.x + threadIdx.x;
    if (i < Z0) {
        g_deg[i] = 0;
    } else if (i < C0) {
        int j = i - Z0;
        g_h[j] = __float2half(x[j]);
    } else if (i < W0) {           // basis0: DO=128
        int j = i - C0;
        int n = j & 127, kk = j >> 7;           // n fast -> coalesced read
        g_Bh[n * 264 + kk] =
            __float2half(b0[((kk >> 7) * 128 + (kk & 127)) * 128 + n]);
    } else if (i < W1) {           // basis1: DO=128
        int j = i - W0;
        int n = j & 127, kk = j >> 7;
        g_Bh[128 * 264 + n * 264 + kk] =
            __float2half(b1[((kk >> 7) * 128 + (kk & 127)) * 128 + n]);
    } else if (i < W2) {           // basis2: DO=64
        int j = i - W1;
        int n = j & 63, kk = j >> 6;
        g_Bh[256 * 264 + n * 264 + kk] =
            __float2half(b2[((kk >> 7) * 128 + (kk & 127)) * 64 + n]);
    }
}

// ---------------- degree count ----------------
__global__ void k_count(const int* __restrict__ src, const int* __restrict__ dst) {
    int i = blockIdx.x * blockDim.x + threadIdx.x;
    if (i >= RR * EE) return;
    int r = i / EE;
    atomicAdd(&g_deg[r * NN + src[i]], 1);        // out-degree (r,s)
    atomicAdd(&g_deg[NR + r * NN + dst[i]], 1);   // in-degree  (r,d)
}

// ---------------- CSR build (counting sort by (r,dst)) + norms ----------------
// scan1: norms + per-block INCLUSIVE scan; writes local-exclusive prefix to g_off
__global__ void __launch_bounds__(1024)
k_scan1() {
    __shared__ int sh[1024];
    int i = blockIdx.x * 1024 + threadIdx.x;
    int t = threadIdx.x;
    int din = 0;
    if (i < NR) {
        int dout = g_deg[i];
        din = g_deg[NR + i];
        g_norm[i]      = rsqrtf((float)max(dout, 1));
        g_norm[NR + i] = rsqrtf((float)max(din, 1));
    }
    sh[t] = din;
    __syncthreads();
    for (int s = 1; s < 1024; s <<= 1) {
        int u = (t >= s) ? sh[t - s] : 0;
        __syncthreads();
        sh[t] += u;
        __syncthreads();
    }
    if (i < NR) g_off[i] = sh[t] - din;      // local exclusive prefix
    if (t == 1023) g_bsum[blockIdx.x] = sh[1023];   // block total
}

// scanfix: add cross-block prefix to local prefixes; init cursors + total
__global__ void __launch_bounds__(1024)
k_scanfix() {
    __shared__ int sb[256];
    int t = threadIdx.x;
    if (t < 256) sb[t] = (t < NB1) ? g_bsum[t] : 0;
    __syncthreads();
    if (t < 256) {   // inclusive scan of the 196 block sums
        for (int s = 1; s < 256; s <<= 1) {
            int v = (t >= s) ? sb[t - s] : 0;
            __syncthreads();
            sb[t] += v;
            __syncthreads();
        }
    } else {
        for (int s = 1; s < 256; s <<= 1) { __syncthreads(); __syncthreads(); }
    }
    int blkpref = (blockIdx.x == 0) ? 0 : sb[blockIdx.x - 1];

    int i = blockIdx.x * 1024 + t;
    if (i < NR) {
        int ex = g_off[i] + blkpref;
        g_off[i] = ex;
        g_cur[i] = ex;
    }
    if (i == 0) g_off[NR] = sb[NB1 - 1];     // grand total
}

__global__ void k_fill(const int* __restrict__ src, const int* __restrict__ dst) {
    int i = blockIdx.x * blockDim.x + threadIdx.x;
    if (i >= RR * EE) return;
    int r = i / EE;
    int s = src[i], d = dst[i];
    int pos = atomicAdd(&g_cur[r * NN + d], 1);
    unsigned nh = (unsigned)__half_as_ushort(__float2half(g_norm[r * NN + s]));
    g_epk[pos] = (unsigned)s | (nh << 16);   // src:u16 | fp16(n_out):u16
}

// ---------------- aggregation: warp per node, per-relation segments (R7) -------
__device__ __forceinline__ void accA(float4& acc, uint2 pk, float we) {
    float2 f0 = __half22float2(*(__half2*)&pk.x);
    float2 f1 = __half22float2(*(__half2*)&pk.y);
    acc.x = fmaf(we, f0.x, acc.x);
    acc.y = fmaf(we, f0.y, acc.y);
    acc.z = fmaf(we, f1.x, acc.z);
    acc.w = fmaf(we, f1.y, acc.w);
}
__device__ __forceinline__ float wOf(unsigned p) {
    return __half2float(__ushort_as_half((unsigned short)(p >> 16)));
}

__global__ void __launch_bounds__(256)
k_agg(const __half* __restrict__ h, const float* __restrict__ coeff,
      __half* __restrict__ G) {
    int w = (blockIdx.x * 256 + threadIdx.x) >> 5;   // node id
    int lane = threadIdx.x & 31;
    if (w >= NN) return;
    float4 g0 = make_float4(0.f, 0.f, 0.f, 0.f);
    float4 g1 = make_float4(0.f, 0.f, 0.f, 0.f);
#pragma unroll
    for (int r = 0; r < RR; r++) {
        int idx = r * NN + w;
        int beg = g_off[idx], end = g_off[idx + 1];
        float4 acc = make_float4(0.f, 0.f, 0.f, 0.f);
        int e = beg;
        // 4-way unroll: 4 descriptor loads, then 4 independent gathers (MLP=4)
        for (; e + 4 <= end; e += 4) {
            unsigned p0 = g_epk[e],     p1 = g_epk[e + 1];
            unsigned p2 = g_epk[e + 2], p3 = g_epk[e + 3];
            uint2 a = ((const uint2*)(h + (p0 & 0xFFFFu) * 128))[lane];
            uint2 b = ((const uint2*)(h + (p1 & 0xFFFFu) * 128))[lane];
            uint2 c = ((const uint2*)(h + (p2 & 0xFFFFu) * 128))[lane];
            uint2 d = ((const uint2*)(h + (p3 & 0xFFFFu) * 128))[lane];
            accA(acc, a, wOf(p0));
            accA(acc, b, wOf(p1));
            accA(acc, c, wOf(p2));
            accA(acc, d, wOf(p3));
        }
        for (; e < end; e++) {
            unsigned p = g_epk[e];
            uint2 a = ((const uint2*)(h + (p & 0xFFFFu) * 128))[lane];
            accA(acc, a, wOf(p));
        }
        float ni = g_norm[NR + idx];
        float s0 = ni * coeff[2 * r];
        float s1 = ni * coeff[2 * r + 1];
        g0.x = fmaf(s0, acc.x, g0.x); g0.y = fmaf(s0, acc.y, g0.y);
        g0.z = fmaf(s0, acc.z, g0.z); g0.w = fmaf(s0, acc.w, g0.w);
        g1.x = fmaf(s1, acc.x, g1.x); g1.y = fmaf(s1, acc.y, g1.y);
        g1.z = fmaf(s1, acc.z, g1.z); g1.w = fmaf(s1, acc.w, g1.w);
    }
    __half2 h0 = __floats2half2_rn(g0.x, g0.y), h1 = __floats2half2_rn(g0.z, g0.w);
    __half2 h2 = __floats2half2_rn(g1.x, g1.y), h3 = __floats2half2_rn(g1.z, g1.w);
    uint2 u0, u1;
    u0.x = *(unsigned*)&h0; u0.y = *(unsigned*)&h1;
    u1.x = *(unsigned*)&h2; u1.y = *(unsigned*)&h3;
    ((uint2*)(G + w * 256))[lane]       = u0;   // G0
    ((uint2*)(G + w * 256 + 128))[lane] = u1;   // G1
}

// ---------------- tensor-core GEMM: G[N,256](fp16) @ B -> out ----------------
// A prefetch + double-buffered A staging: one __syncthreads per k-step.
template<int DO, bool RELU, bool TOHALF>
__global__ void __launch_bounds__(256)
k_gemm_tc(const __half* __restrict__ G, const __half* __restrict__ Bh,
          void* __restrict__ outp) {
    __shared__ __half Bs[64 * 264];      // [n][k], stride 264 halves
    __shared__ __half As[2][128 * 24];   // double-buffered A staging

    int tid  = threadIdx.x;
    int warp = tid >> 5, lane = tid & 31;
    int row0 = blockIdx.x * 128;
    int col0 = blockIdx.y * 64;

    const uint4* gB = (const uint4*)(Bh + col0 * 264);
    for (int i = tid; i < 64 * 33; i += 256)
        ((uint4*)Bs)[i] = gB[i];

    float acc[8][4];
#pragma unroll
    for (int n = 0; n < 8; n++)
#pragma unroll
        for (int j = 0; j < 4; j++) acc[n][j] = 0.f;

    int arow = tid >> 1, aseg = tid & 1;
    int grow = row0 + arow;
    const __half* gA = G + grow * 256 + aseg * 8;
    __half* asd0 = &As[0][arow * 24 + aseg * 8];
    __half* asd1 = &As[1][arow * 24 + aseg * 8];
    bool aok = grow < NN;

    unsigned ald0 = (unsigned)__cvta_generic_to_shared(
        &As[0][(warp * 16 + (lane & 15)) * 24 + (lane >> 4) * 8]);
    unsigned ald1 = ald0 + 128 * 24 * 2;
    int bn = lane >> 2, bk = (lane & 3) * 2;

    // prologue: stage k-step 0 into buf0, prefetch k-step 1
    uint4 v = make_uint4(0u, 0u, 0u, 0u);
    if (aok) v = *(const uint4*)gA;
    *(uint4*)asd0 = v;
    v = make_uint4(0u, 0u, 0u, 0u);
    if (aok) v = *(const uint4*)(gA + 16);
    __syncthreads();   // covers Bs staging + buf0

    for (int ks = 0; ks < 16; ks++) {
        int k0 = ks * 16;
        // stage next k-step into the other buffer (read last at ks-1, safe)
        if (ks < 15) {
            *(uint4*)(((ks + 1) & 1) ? asd1 : asd0) = v;
            if (ks < 14) {
                v = make_uint4(0u, 0u, 0u, 0u);
                if (aok) v = *(const uint4*)(gA + (ks + 2) * 16);
            }
        }

        unsigned a0, a1, a2, a3;
        asm volatile("ldmatrix.sync.aligned.m8n8.x4.shared.b16 {%0,%1,%2,%3}, [%4];"
                     : "=r"(a0), "=r"(a1), "=r"(a2), "=r"(a3)
                     : "r"((ks & 1) ? ald1 : ald0));
#pragma unroll
        for (int nt = 0; nt < 8; nt++) {
            const __half* bp = Bs + (nt * 8 + bn) * 264 + k0 + bk;
            unsigned b0 = *(const unsigned*)bp;
            unsigned b1 = *(const unsigned*)(bp + 8);
            asm volatile(
                "mma.sync.aligned.m16n8k16.row.col.f32.f16.f16.f32 "
                "{%0,%1,%2,%3}, {%4,%5,%6,%7}, {%8,%9}, {%0,%1,%2,%3};"
                : "+f"(acc[nt][0]), "+f"(acc[nt][1]), "+f"(acc[nt][2]), "+f"(acc[nt][3])
                : "r"(a0), "r"(a1), "r"(a2), "r"(a3), "r"(b0), "r"(b1));
        }
        __syncthreads();   // publish next buffer / retire this one
    }

    int rlo = row0 + warp * 16 + (lane >> 2);
    int cb  = col0 + (lane & 3) * 2;
#pragma unroll
    for (int nt = 0; nt < 8; nt++) {
        int c = cb + nt * 8;
        float d0 = acc[nt][0], d1 = acc[nt][1], d2 = acc[nt][2], d3 = acc[nt][3];
        if (RELU) {
            d0 = fmaxf(d0, 0.f); d1 = fmaxf(d1, 0.f);
            d2 = fmaxf(d2, 0.f); d3 = fmaxf(d3, 0.f);
        }
        if (TOHALF) {
            __half* o = (__half*)outp;
            if (rlo < NN)     *(__half2*)(o + rlo * DO + c)       = __floats2half2_rn(d0, d1);
            if (rlo + 8 < NN) *(__half2*)(o + (rlo + 8) * DO + c) = __floats2half2_rn(d2, d3);
        } else {
            float* o = (float*)outp;
            if (rlo < NN)     { o[rlo * DO + c] = d0;       o[rlo * DO + c + 1] = d1; }
            if (rlo + 8 < NN) { o[(rlo + 8) * DO + c] = d2; o[(rlo + 8) * DO + c + 1] = d3; }
        }
    }
}

// ---------------- launch ----------------
extern "C" void kernel_launch(void* const* d_in, const int* in_sizes, int n_in,
                              void* d_out, int out_size) {
    const float* x   = (const float*)d_in[0];
    const int*   src = (const int*)  d_in[1];
    const int*   dst = (const int*)  d_in[2];
    const float* b0  = (const float*)d_in[3];
    const float* c0  = (const float*)d_in[4];
    const float* b1  = (const float*)d_in[5];
    const float* c1  = (const float*)d_in[6];
    const float* b2  = (const float*)d_in[7];
    const float* c2  = (const float*)d_in[8];
    float* out = (float*)d_out;

    __half *h, *G, *Bh;
    cudaGetSymbolAddress((void**)&h,  g_h);
    cudaGetSymbolAddress((void**)&G,  g_G);
    cudaGetSymbolAddress((void**)&Bh, g_Bh);
    __half* Bh0 = Bh;
    __half* Bh1 = Bh + 128 * 264;
    __half* Bh2 = Bh + 256 * 264;

    const int preN    = 2 * NR + NN * 128 + 128 * 256 + 128 * 256 + 64 * 256;
    const int edgeTh  = (RR * EE + 255) / 256;
    const int aggGrid = (NN * 32 + 255) / 256;       // 1 warp per node
    const dim3 gemm2(391, 2), gemm1(391, 1);

    // preprocessing (every call: deterministic)
    k_pre<<<(preN + 255) / 256, 256>>>(x, b0, b1, b2);
    k_count<<<edgeTh, 256>>>(src, dst);
    k_scan1<<<NB1, 1024>>>();
    k_scanfix<<<NB1, 1024>>>();
    k_fill<<<edgeTh, 256>>>(src, dst);

    // layer 0
    k_agg<<<aggGrid, 256>>>(h, c0, G);
    k_gemm_tc<128, true, true><<<gemm2, 256>>>(G, Bh0, h);
    // layer 1
    k_agg<<<aggGrid, 256>>>(h, c1, G);
    k_gemm_tc<128, true, true><<<gemm2, 256>>>(G, Bh1, h);
    // layer 2: final, fp32, no relu
    k_agg<<<aggGrid, 256>>>(h, c2, G);
    k_gemm_tc<64, false, false><<<gemm1, 256>>>(G, Bh2, out);
}